// round 3
// baseline (speedup 1.0000x reference)
#include <cuda_runtime.h>

#define NANG  4
#define NELEM 128
#define NZ    192
#define NX    192
#define NSAMP 2048
#define NPIX  (NZ * NX)

#define PI_F      3.14159265359f
#define HALF_PI_F 1.57079632679f
#define FS_F      20832000.0f
#define C_F       1540.0f
#define FDEMOD_F  5208000.0f
#define FSoC      (FS_F / C_F)

// Scratch (static device globals -- no allocation)
__device__ float2 g_iq[NANG * NELEM * NSAMP];   // interleaved (i,q), 8 MB
__device__ float  g_acc[NANG * 2][NPIX];        // per-angle partial sums

// ---------------------------------------------------------------------------
// Pass 1: interleave idata/qdata into float2. 8 floats per thread, float4 I/O.
// ---------------------------------------------------------------------------
__global__ __launch_bounds__(256)
void interleave_k(const float* __restrict__ id,
                  const float* __restrict__ qd) {
    int i = (blockIdx.x * blockDim.x + threadIdx.x) * 8;   // total divisible by 8
    float4 a0 = *(const float4*)(id + i);
    float4 a1 = *(const float4*)(id + i + 4);
    float4 b0 = *(const float4*)(qd + i);
    float4 b1 = *(const float4*)(qd + i + 4);
    float4* dst = (float4*)(g_iq + i);
    dst[0] = make_float4(a0.x, b0.x, a0.y, b0.y);
    dst[1] = make_float4(a0.z, b0.z, a0.w, b0.w);
    dst[2] = make_float4(a1.x, b1.x, a1.y, b1.y);
    dst[3] = make_float4(a1.z, b1.z, a1.w, b1.w);
}

// ---------------------------------------------------------------------------
// One element's contribution to one pixel: lerp gather + exact (pi/2)*delay
// rotation (quadrant from i0&3, MUFU sincos on frac*pi/2 in [0,pi/2)).
// ---------------------------------------------------------------------------
__device__ __forceinline__ void contrib(const float2* __restrict__ row,
                                        float delay, float& ai, float& aq) {
    const float i0f  = floorf(delay);
    const float frac = delay - i0f;
    const int   i0   = (int)i0f;

    float2 p0 = make_float2(0.0f, 0.0f);
    float2 p1 = make_float2(0.0f, 0.0f);
    if ((unsigned)i0 < (unsigned)NSAMP)       p0 = __ldg(row + i0);
    if ((unsigned)(i0 + 1) < (unsigned)NSAMP) p1 = __ldg(row + i0 + 1);

    const float ifoc = fmaf(frac, p1.x - p0.x, p0.x);
    const float qfoc = fmaf(frac, p1.y - p0.y, p0.y);

    const float targ = frac * HALF_PI_F;
    const float s0 = __sinf(targ);
    const float c0 = __cosf(targ);
    const int   q  = i0 & 3;
    float ct = (q & 1) ? s0 : c0;
    float st = (q & 1) ? c0 : s0;
    const unsigned negc = (unsigned)((q + 1) & 2) << 30; // negate cos for q in {1,2}
    const unsigned negs = (unsigned)(q & 2) << 30;       // negate sin for q in {2,3}
    ct = __int_as_float(__float_as_int(ct) ^ negc);
    st = __int_as_float(__float_as_int(st) ^ negs);

    ai += ifoc * ct - qfoc * st;
    aq += qfoc * ct + ifoc * st;
}

// ---------------------------------------------------------------------------
// Pass 2: main DAS. Tile = 32(x) x 16(z) per block; each thread owns 2 z-pixels
// (iz, iz+8) for load-latency ILP. Element loop runs only over the analytic
// aperture range [eLo,eHi] (mask proven contiguous), exact predicate inside.
// ---------------------------------------------------------------------------
__global__ __launch_bounds__(256)
void das_k(const float* __restrict__ grid,
           const float* __restrict__ angles,
           const float* __restrict__ ele,
           const float* __restrict__ tz) {
    __shared__ float sex[NELEM];
    int t = threadIdx.x;
    if (t < NELEM) sex[t] = ele[t * 3];      // ele_pos[e,0]
    __syncthreads();

    const int a   = blockIdx.z;
    const int ix  = blockIdx.x * 32 + (t & 31);
    const int iz0 = blockIdx.y * 16 + (t >> 5);
    const int iz1 = iz0 + 8;
    const int p0  = iz0 * NX + ix;
    const int p1  = iz1 * NX + ix;

    const float x  = grid[3 * p0 + 0];
    const float z0 = grid[3 * p0 + 2];
    const float z1 = grid[3 * p1 + 2];       // z1 > z0 always

    const float ang = angles[a];
    const float sa = sinf(ang);
    const float ca = cosf(ang);
    const float ta = tanf(ang);
    const float tzc = tz[a] * C_F;

    const float txd0 = (x * sa + z0 * ca + tzc) * FSoC;
    const float txd1 = (x * sa + z1 * ca + tzc) * FSoC;

    const float ex0 = sex[0];
    const float exN = sex[NELEM - 1];

    const float xp0 = x - z0 * ta;
    const float xp1 = x - z1 * ta;
    const bool tx0 = (xp0 >= ex0 * 1.2f) && (xp0 <= exN * 1.2f);
    const bool tx1 = (xp1 >= ex0 * 1.2f) && (xp1 <= exN * 1.2f);

    float ai0 = 0.0f, aq0 = 0.0f, ai1 = 0.0f, aq1 = 0.0f;

    if (tx0 | tx1) {
        const float pitch = sex[1] - sex[0];
        const float inv_pitch = 1.0f / pitch;
        // aperture of the deeper pixel (z1) is the wider one; +/-1 slack
        int eLo = (int)floorf((x - 0.5f * z1 - ex0) * inv_pitch) - 1;
        int eHi = (int)ceilf((x + 0.5f * z1 - ex0) * inv_pitch) + 1;
        eLo = eLo < 0 ? 0 : eLo;
        eHi = eHi > NELEM - 1 ? NELEM - 1 : eHi;

        const float zz0 = z0 * z0;
        const float zz1 = z1 * z1;
        const float2* __restrict__ base = g_iq + (size_t)a * NELEM * NSAMP;

        #pragma unroll 2
        for (int e = eLo; e <= eHi; e++) {
            const float ex  = sex[e];
            const float vx  = x - ex;
            const float avx = fabsf(vx);
            const float vx2 = vx * vx;
            const float2* __restrict__ row = base + e * NSAMP;

            if (tx0 && (z0 > 2.0f * avx)) {
                const float r2 = vx2 + zz0;
                const float rx = r2 * rsqrtf(r2) * FSoC;
                contrib(row, txd0 + rx, ai0, aq0);
            }
            if (tx1 && (z1 > 2.0f * avx)) {
                const float r2 = vx2 + zz1;
                const float rx = r2 * rsqrtf(r2) * FSoC;
                contrib(row, txd1 + rx, ai1, aq1);
            }
        }
    }

    g_acc[a * 2 + 0][p0] = ai0;
    g_acc[a * 2 + 1][p0] = aq0;
    g_acc[a * 2 + 0][p1] = ai1;
    g_acc[a * 2 + 1][p1] = aq1;
}

// ---------------------------------------------------------------------------
// Pass 3: sum angle partials + deferred pixel-constant rotation
// phi(z) = -4*pi*FDEMOD*z/C (accurate sincosf, large argument).
// ---------------------------------------------------------------------------
__global__ void reduce_k(const float* __restrict__ grid,
                         float* __restrict__ out) {
    int p = blockIdx.x * blockDim.x + threadIdx.x;
    if (p >= NPIX) return;
    float ai = g_acc[0][p] + g_acc[2][p] + g_acc[4][p] + g_acc[6][p];
    float aq = g_acc[1][p] + g_acc[3][p] + g_acc[5][p] + g_acc[7][p];
    const float z = grid[3 * p + 2];
    const float phi = (-4.0f * PI_F * FDEMOD_F / C_F) * z;
    float sb, cb;
    sincosf(phi, &sb, &cb);
    out[p]        = ai * cb - aq * sb;   // idas
    out[NPIX + p] = aq * cb + ai * sb;   // qdas
}

extern "C" void kernel_launch(void* const* d_in, const int* in_sizes, int n_in,
                              void* d_out, int out_size) {
    const float* idata  = (const float*)d_in[0];
    const float* qdata  = (const float*)d_in[1];
    const float* grid   = (const float*)d_in[2];
    const float* angles = (const float*)d_in[3];
    const float* ele    = (const float*)d_in[4];
    const float* tz     = (const float*)d_in[5];

    int total = NANG * NELEM * NSAMP;              // 1,048,576
    interleave_k<<<total / (256 * 8), 256>>>(idata, qdata);

    dim3 g(NX / 32, NZ / 16, NANG);
    das_k<<<g, 256>>>(grid, angles, ele, tz);

    reduce_k<<<(NPIX + 255) / 256, 256>>>(grid, (float*)d_out);
}

// round 5
// speedup vs baseline: 1.5137x; 1.5137x over previous
#include <cuda_runtime.h>

#define NANG  4
#define NELEM 128
#define NZ    192
#define NX    192
#define NSAMP 2048
#define NPIX  (NZ * NX)

#define PI_F      3.14159265359f
#define HALF_PI_F 1.57079632679f
#define FS_F      20832000.0f
#define C_F       1540.0f
#define FDEMOD_F  5208000.0f
#define FSoC      (FS_F / C_F)

// Scratch (static device globals -- no allocation)
__device__ float2 g_iq[NANG * NELEM * NSAMP];   // interleaved (i,q), 8 MB
__device__ float  g_acc[NANG * 2][NPIX];        // per-angle partial sums

// ---------------------------------------------------------------------------
// Pass 1: interleave idata/qdata into float2. 4 floats/thread, float4 I/O.
// ---------------------------------------------------------------------------
__global__ __launch_bounds__(256)
void interleave_k(const float* __restrict__ id,
                  const float* __restrict__ qd) {
    int i = (blockIdx.x * blockDim.x + threadIdx.x) * 4;   // total divisible by 4
    float4 a = *(const float4*)(id + i);
    float4 b = *(const float4*)(qd + i);
    float4* dst = (float4*)(g_iq + i);
    dst[0] = make_float4(a.x, b.x, a.y, b.y);
    dst[1] = make_float4(a.z, b.z, a.w, b.w);
}

// ---------------------------------------------------------------------------
// One element contribution (branchless): lerp gather + exact (pi/2)*delay
// rotation (quadrant from i0&3, MUFU sincos on frac*pi/2). keep=false lanes
// get zero loads -> zero contribution regardless of the trig values.
// ---------------------------------------------------------------------------
__device__ __forceinline__ void contrib(const float2* __restrict__ row,
                                        float delay, bool keep,
                                        float& ai, float& aq) {
    const int   i0   = __float2int_rd(delay);
    const float frac = delay - (float)i0;

    float2 p0 = make_float2(0.0f, 0.0f);
    float2 p1 = make_float2(0.0f, 0.0f);
    const bool v0 = keep & ((unsigned)i0 < (unsigned)NSAMP);
    const bool v1 = keep & ((unsigned)(i0 + 1) < (unsigned)NSAMP);
    if (v0) p0 = __ldg(row + i0);
    if (v1) p1 = __ldg(row + i0 + 1);

    const float ifoc = fmaf(frac, p1.x - p0.x, p0.x);
    const float qfoc = fmaf(frac, p1.y - p0.y, p0.y);

    const float targ = frac * HALF_PI_F;
    const float s0 = __sinf(targ);
    const float c0 = __cosf(targ);
    const int   q  = i0 & 3;
    float ct = (q & 1) ? s0 : c0;
    float st = (q & 1) ? c0 : s0;
    const unsigned negc = (unsigned)((q + 1) & 2) << 30; // negate cos for q in {1,2}
    const unsigned negs = (unsigned)(q & 2) << 30;       // negate sin for q in {2,3}
    ct = __int_as_float(__float_as_int(ct) ^ negc);
    st = __int_as_float(__float_as_int(st) ^ negs);

    ai += ifoc * ct - qfoc * st;
    aq += qfoc * ct + ifoc * st;
}

// ---------------------------------------------------------------------------
// Pass 2: main DAS. One thread per pixel; warp = 32 consecutive x at fixed z.
// Element loop bounds are WARP-UNIFORM (derived from the warp's x-window and
// its single z), so all lanes walk the same element row together and gathers
// stay coalesced. Per-lane mask handled branchlessly inside contrib().
// ---------------------------------------------------------------------------
__global__ __launch_bounds__(256)
void das_k(const float* __restrict__ grid,
           const float* __restrict__ angles,
           const float* __restrict__ ele,
           const float* __restrict__ tz) {
    __shared__ float sex[NELEM];
    int t = threadIdx.x;                     // tile = 32(x) x 8(z)
    if (t < NELEM) sex[t] = ele[t * 3];      // ele_pos[e,0]
    __syncthreads();

    const int a  = blockIdx.z;
    const int ix = blockIdx.x * 32 + (t & 31);
    const int iz = blockIdx.y * 8  + (t >> 5);
    const int p  = iz * NX + ix;

    const float x = grid[3 * p + 0];
    const float z = grid[3 * p + 2];         // uniform within a warp

    const float ang = angles[a];
    const float sa = sinf(ang);
    const float ca = cosf(ang);
    const float ta = tanf(ang);

    const float txdel = (x * sa + z * ca + tz[a] * C_F) * FSoC;

    const float ex0 = sex[0];
    const float exN = sex[NELEM - 1];

    const float xproj = x - z * ta;
    const bool txapo = (xproj >= ex0 * 1.2f) && (xproj <= exN * 1.2f);

    float ai = 0.0f, aq = 0.0f;

    if (__any_sync(0xffffffffu, txapo)) {
        // warp-uniform element range from the warp's x window and z
        const float x_lo = __shfl_sync(0xffffffffu, x, 0);
        const float x_hi = __shfl_sync(0xffffffffu, x, 31);
        const float inv_pitch = 1.0f / (sex[1] - sex[0]);
        const float hz = 0.5f * z;
        int eLo = (int)floorf((x_lo - hz - ex0) * inv_pitch) - 1;
        int eHi = (int)ceilf ((x_hi + hz - ex0) * inv_pitch) + 1;
        eLo = eLo < 0 ? 0 : eLo;
        eHi = eHi > NELEM - 1 ? NELEM - 1 : eHi;

        const float zz = z * z;
        const float2* __restrict__ base = g_iq + (size_t)a * NELEM * NSAMP;

        #pragma unroll 4
        for (int e = eLo; e <= eHi; e++) {
            const float ex  = sex[e];
            const float vx  = x - ex;
            const bool keep = txapo & (z > 2.0f * fabsf(vx));
            const float r2  = fmaf(vx, vx, zz);
            const float delay = fmaf(r2 * rsqrtf(r2), FSoC, txdel);
            contrib(base + e * NSAMP, delay, keep, ai, aq);
        }
    }

    g_acc[a * 2 + 0][p] = ai;
    g_acc[a * 2 + 1][p] = aq;
}

// ---------------------------------------------------------------------------
// Pass 3: sum angle partials + deferred pixel-constant rotation
// phi(z) = -4*pi*FDEMOD*z/C (accurate sincosf, large argument).
// ---------------------------------------------------------------------------
__global__ void reduce_k(const float* __restrict__ grid,
                         float* __restrict__ out) {
    int p = blockIdx.x * blockDim.x + threadIdx.x;
    if (p >= NPIX) return;
    float ai = g_acc[0][p] + g_acc[2][p] + g_acc[4][p] + g_acc[6][p];
    float aq = g_acc[1][p] + g_acc[3][p] + g_acc[5][p] + g_acc[7][p];
    const float z = grid[3 * p + 2];
    const float phi = (-4.0f * PI_F * FDEMOD_F / C_F) * z;
    float sb, cb;
    sincosf(phi, &sb, &cb);
    out[p]        = ai * cb - aq * sb;   // idas
    out[NPIX + p] = aq * cb + ai * sb;   // qdas
}

extern "C" void kernel_launch(void* const* d_in, const int* in_sizes, int n_in,
                              void* d_out, int out_size) {
    const float* idata  = (const float*)d_in[0];
    const float* qdata  = (const float*)d_in[1];
    const float* grid   = (const float*)d_in[2];
    const float* angles = (const float*)d_in[3];
    const float* ele    = (const float*)d_in[4];
    const float* tz     = (const float*)d_in[5];

    int total = NANG * NELEM * NSAMP;              // 1,048,576
    interleave_k<<<total / (256 * 4), 256>>>(idata, qdata);

    dim3 g(NX / 32, NZ / 8, NANG);
    das_k<<<g, 256>>>(grid, angles, ele, tz);

    reduce_k<<<(NPIX + 255) / 256, 256>>>(grid, (float*)d_out);
}

// round 7
// speedup vs baseline: 1.6554x; 1.0936x over previous
#include <cuda_runtime.h>

#define NANG  4
#define NELEM 128
#define NZ    192
#define NX    192
#define NSAMP 2048
#define NPIX  (NZ * NX)

#define PI_F      3.14159265359f
#define HALF_PI_F 1.57079632679f
#define FS_F      20832000.0f
#define C_F       1540.0f
#define FDEMOD_F  5208000.0f
#define FSoC      (FS_F / C_F)

// Scratch (static device globals -- no allocation)
__device__ float2 g_iq[NANG * NELEM * NSAMP];   // interleaved (i,q), 8 MB
__device__ float  g_acc[NANG * 2][NPIX];        // per-angle partial sums

// ---------------------------------------------------------------------------
// Pass 1: interleave idata/qdata into float2. 2 floats/thread, 16K warps so
// outstanding-load bytes exceed the BW*latency product (~2.5 MB).
// ---------------------------------------------------------------------------
__global__ __launch_bounds__(256)
void interleave_k(const float* __restrict__ id,
                  const float* __restrict__ qd) {
    int i = (blockIdx.x * blockDim.x + threadIdx.x) * 2;
    float2 a = *(const float2*)(id + i);
    float2 b = *(const float2*)(qd + i);
    *(float4*)(g_iq + i) = make_float4(a.x, b.x, a.y, b.y);
}

// ---------------------------------------------------------------------------
// One element contribution (branchless): lerp gather + exact (pi/2)*delay
// rotation (quadrant from i0&3, MUFU sincos on frac*pi/2). keep=false lanes
// get zero loads -> zero contribution regardless of the trig values.
// ---------------------------------------------------------------------------
__device__ __forceinline__ void contrib(const float2* __restrict__ row,
                                        float delay, bool keep,
                                        float& ai, float& aq) {
    const int   i0   = __float2int_rd(delay);
    const float frac = delay - (float)i0;

    float2 p0 = make_float2(0.0f, 0.0f);
    float2 p1 = make_float2(0.0f, 0.0f);
    const bool v0 = keep & ((unsigned)i0 < (unsigned)NSAMP);
    const bool v1 = keep & ((unsigned)(i0 + 1) < (unsigned)NSAMP);
    if (v0) p0 = __ldg(row + i0);
    if (v1) p1 = __ldg(row + i0 + 1);

    const float ifoc = fmaf(frac, p1.x - p0.x, p0.x);
    const float qfoc = fmaf(frac, p1.y - p0.y, p0.y);

    const float targ = frac * HALF_PI_F;
    const float s0 = __sinf(targ);
    const float c0 = __cosf(targ);
    const int   q  = i0 & 3;
    float ct = (q & 1) ? s0 : c0;
    float st = (q & 1) ? c0 : s0;
    const unsigned negc = (unsigned)((q + 1) & 2) << 30; // negate cos for q in {1,2}
    const unsigned negs = (unsigned)(q & 2) << 30;       // negate sin for q in {2,3}
    ct = __int_as_float(__float_as_int(ct) ^ negc);
    st = __int_as_float(__float_as_int(st) ^ negs);

    ai += ifoc * ct - qfoc * st;
    aq += qfoc * ct + ifoc * st;
}

// ---------------------------------------------------------------------------
// Pass 2: main DAS. One thread per pixel; warp = 32 consecutive x at fixed z.
// Element loop bounds are WARP-UNIFORM, so all lanes walk the same element
// row together (coalesced gathers). vx is computed EXACTLY per element from
// sex[e] (a recurrence drifts into the keep-threshold and flips masks).
// ---------------------------------------------------------------------------
__global__ __launch_bounds__(256)
void das_k(const float* __restrict__ grid,
           const float* __restrict__ angles,
           const float* __restrict__ ele,
           const float* __restrict__ tz) {
    __shared__ float sex[NELEM];
    int t = threadIdx.x;                     // tile = 32(x) x 8(z)
    if (t < NELEM) sex[t] = ele[t * 3];      // ele_pos[e,0]
    __syncthreads();

    const int a  = blockIdx.z;
    const int ix = blockIdx.x * 32 + (t & 31);
    const int iz = blockIdx.y * 8  + (t >> 5);
    const int p  = iz * NX + ix;

    const float x = grid[3 * p + 0];
    const float z = grid[3 * p + 2];         // uniform within a warp

    const float ang = angles[a];
    const float sa = sinf(ang);
    const float ca = cosf(ang);
    const float ta = tanf(ang);

    const float txdel = (x * sa + z * ca + tz[a] * C_F) * FSoC;

    const float ex0 = sex[0];
    const float exN = sex[NELEM - 1];

    const float xproj = x - z * ta;
    const bool txapo = (xproj >= ex0 * 1.2f) && (xproj <= exN * 1.2f);

    float ai = 0.0f, aq = 0.0f;

    if (__any_sync(0xffffffffu, txapo)) {
        // warp-uniform element range from the warp's x window and z
        const float x_lo = __shfl_sync(0xffffffffu, x, 0);
        const float x_hi = __shfl_sync(0xffffffffu, x, 31);
        const float inv_pitch = 1.0f / (sex[1] - sex[0]);
        const float hz = 0.5f * z;
        int eLo = (int)floorf((x_lo - hz - ex0) * inv_pitch) - 1;
        int eHi = (int)ceilf ((x_hi + hz - ex0) * inv_pitch) + 1;
        eLo = eLo < 0 ? 0 : eLo;
        eHi = eHi > NELEM - 1 ? NELEM - 1 : eHi;

        const float zz = z * z;
        const float2* __restrict__ row = g_iq + ((size_t)a * NELEM + eLo) * NSAMP;

        #pragma unroll 8
        for (int e = eLo; e <= eHi; e++) {
            const float vx  = x - sex[e];           // exact, matches reference
            const bool keep = txapo & (z > 2.0f * fabsf(vx));
            const float r2  = fmaf(vx, vx, zz);
            const float delay = fmaf(r2 * rsqrtf(r2), FSoC, txdel);
            contrib(row, delay, keep, ai, aq);
            row += NSAMP;
        }
    }

    g_acc[a * 2 + 0][p] = ai;
    g_acc[a * 2 + 1][p] = aq;
}

// ---------------------------------------------------------------------------
// Pass 3: sum angle partials + deferred pixel-constant rotation
// phi(z) = -4*pi*FDEMOD*z/C (accurate sincosf, large argument).
// ---------------------------------------------------------------------------
__global__ void reduce_k(const float* __restrict__ grid,
                         float* __restrict__ out) {
    int p = blockIdx.x * blockDim.x + threadIdx.x;
    if (p >= NPIX) return;
    float ai = g_acc[0][p] + g_acc[2][p] + g_acc[4][p] + g_acc[6][p];
    float aq = g_acc[1][p] + g_acc[3][p] + g_acc[5][p] + g_acc[7][p];
    const float z = grid[3 * p + 2];
    const float phi = (-4.0f * PI_F * FDEMOD_F / C_F) * z;
    float sb, cb;
    sincosf(phi, &sb, &cb);
    out[p]        = ai * cb - aq * sb;   // idas
    out[NPIX + p] = aq * cb + ai * sb;   // qdas
}

extern "C" void kernel_launch(void* const* d_in, const int* in_sizes, int n_in,
                              void* d_out, int out_size) {
    const float* idata  = (const float*)d_in[0];
    const float* qdata  = (const float*)d_in[1];
    const float* grid   = (const float*)d_in[2];
    const float* angles = (const float*)d_in[3];
    const float* ele    = (const float*)d_in[4];
    const float* tz     = (const float*)d_in[5];

    int total = NANG * NELEM * NSAMP;              // 1,048,576
    interleave_k<<<total / (256 * 2), 256>>>(idata, qdata);

    dim3 g(NX / 32, NZ / 8, NANG);
    das_k<<<g, 256>>>(grid, angles, ele, tz);

    reduce_k<<<(NPIX + 255) / 256, 256>>>(grid, (float*)d_out);
}